// round 10
// baseline (speedup 1.0000x reference)
#include <cuda_runtime.h>

// Geometry: (N=2, C=1, D=160, H=192, W=224), win=9, pad=4, zero-padded box sums.
#define NB   2
#define DD   160
#define HH   192
#define WW   224
#define HW   (HH * WW)            // 43008
#define DHW  (DD * HW)            // 6881280
#define VOLI (NB * DHW)           // 13762560
#define PAD  4
#define EPSV 1e-5f
#define SZ   ((size_t)VOLI)

#define CH     64                 // h-chunk per kA-role block
#define NCHK   3                  // H/CH
#define NSTEPS (CH + 2 * PAD)     // 72
#define ROWL   (WW + 2 * PAD)     // 232

#define K3_BLK   336              // blocks per k3 phase: 2*192*224/256
#define NPARTS   3
#define NPART_TOT (NPARTS * K3_BLK)

// Scratch: W+H box-summed fields. float4 = (sumI,sumJ,sumI2,sumJ2), float = sumIJ.
__device__ float4 g_B4[SZ];
__device__ float  g_B1[SZ];
__device__ double g_part[NPART_TOT];

// ---------------------------------------------------------------------------
// Fused kernel: first nA blocks run the kA role (W+H box sums, R7 algorithm),
// remaining blocks run the k3 role (D sliding window + loss + reduction, R7
// algorithm). Roles are resource-complementary (kA: L1/smem-bound, k3:
// DRAM-bound), so co-residency overlaps the two phases.
// ---------------------------------------------------------------------------
__global__ __launch_bounds__(256) void fusedAB(
    const float* __restrict__ I, const float* __restrict__ J,
    int dloA, int ndA, int nA,        // kA: planes d in [dloA, dloA+ndA)
    int d0C, int d1C, int partC)      // k3: outputs d in [d0C, d1C)
{
    __shared__ float4 ringQ[9][ROWL];   // 33,408 B
    __shared__ float  ringS[9][ROWL];   //  8,352 B
    __shared__ float  sI[2][ROWL];
    __shared__ float  sJ[2][ROWL];

    const int t = threadIdx.x;

    if ((int)blockIdx.x < nA) {
        // ------------------------- kA role -------------------------
        const int item = blockIdx.x;
        const int pi = item / NCHK;
        const int chunk = item - pi * NCHK;
        const int n = pi / ndA;
        const int d = dloA + (pi - n * ndA);
        const int plane = n * DD + d;
        const int h0 = chunk * CH;

        const float* Ip = I + (size_t)plane * HW;
        const float* Jp = J + (size_t)plane * HW;
        const size_t obase = (size_t)plane * HW;

        const int wld = t - PAD;
        const bool lane_ok = (t < ROWL);
        const bool ld_ok = lane_ok && ((unsigned)wld < (unsigned)WW);

        if (t < ROWL) {
#pragma unroll
            for (int s = 0; s < 9; s++) {
                ringQ[s][t] = make_float4(0.f, 0.f, 0.f, 0.f);
                ringS[s][t] = 0.f;
            }
        }

        float S0 = 0.f, S1 = 0.f, S2 = 0.f, S3 = 0.f, S4 = 0.f;

        float vi = 0.f, vj = 0.f;
        {
            const int hh = h0 - PAD;
            if (ld_ok && (unsigned)hh < (unsigned)HH) {
                const size_t p = (size_t)hh * WW + wld;
                vi = Ip[p]; vj = Jp[p];
            }
        }

        int rs = 0;
#pragma unroll 2
        for (int step = 0; step < NSTEPS; step++) {
            const int buf = step & 1;

            if (lane_ok) {
                sI[buf][t] = vi;
                sJ[buf][t] = vj;
            }
            {
                const int hh = h0 - PAD + step + 1;
                vi = 0.f; vj = 0.f;
                if (ld_ok && (unsigned)hh < (unsigned)HH) {
                    const size_t p = (size_t)hh * WW + wld;
                    vi = Ip[p]; vj = Jp[p];
                }
            }

            __syncthreads();

            if (t < WW) {
                float v0 = 0.f, v1 = 0.f, v2 = 0.f, v3 = 0.f, v4 = 0.f;
#pragma unroll
                for (int q = 0; q < 9; q++) {
                    const float a = sI[buf][t + q];
                    const float b = sJ[buf][t + q];
                    v0 += a; v1 += b;
                    v2 += a * a; v3 += b * b; v4 += a * b;
                }
                const float4 o4 = ringQ[rs][t];
                const float  o1 = ringS[rs][t];
                S0 += v0 - o4.x;
                S1 += v1 - o4.y;
                S2 += v2 - o4.z;
                S3 += v3 - o4.w;
                S4 += v4 - o1;
                ringQ[rs][t] = make_float4(v0, v1, v2, v3);
                ringS[rs][t] = v4;

                if (step >= 2 * PAD) {
                    const int ho = h0 + step - 2 * PAD;
                    const size_t idx = obase + (size_t)ho * WW + t;
                    g_B4[idx] = make_float4(S0, S1, S2, S3);
                    g_B1[idx] = S4;
                }
            }
            rs = (rs == 8) ? 0 : rs + 1;
        }
    } else {
        // ------------------------- k3 role -------------------------
        const int bidC = blockIdx.x - nA;
        const int gt = bidC * 256 + t;      // (n, h, w) index, gt < 86016 always
        const int w = gt % WW;
        int r = gt / WW;
        const int h = r % HH;
        const int n = r / HH;
        const size_t base = (size_t)n * DHW + (size_t)h * WW + w;

        float S0 = 0.f, S1 = 0.f, S2 = 0.f, S3 = 0.f, S4 = 0.f;
#pragma unroll
        for (int k = -PAD; k <= PAD; k++) {
            const int dd = d0C + k;
            if ((unsigned)dd < (unsigned)DD) {
                const size_t p = base + (size_t)dd * HW;
                const float4 f = g_B4[p];
                S0 += f.x; S1 += f.y; S2 += f.z; S3 += f.w;
                S4 += g_B1[p];
            }
        }

        const float ws = 729.f, inv_ws = 1.f / 729.f;
        float local = 0.f;

#pragma unroll 4
        for (int d = d0C; d < d1C; d++) {
            const float ui = S0 * inv_ws;
            const float uj = S1 * inv_ws;
            const float cross = S4 - uj * S0 - ui * S1 + ui * uj * ws;
            const float iv = fmaxf(S2 - 2.f * ui * S0 + ui * ui * ws, EPSV);
            const float jv = fmaxf(S3 - 2.f * uj * S1 + uj * uj * ws, EPSV);
            local += (cross * cross) / (iv * jv);

            const int da = d + PAD + 1;
            const int ds = d - PAD;
            if (da < DD) {
                const size_t q = base + (size_t)da * HW;
                const float4 f = g_B4[q];
                S0 += f.x; S1 += f.y; S2 += f.z; S3 += f.w;
                S4 += g_B1[q];
            }
            if (ds >= 0) {
                const size_t q = base + (size_t)ds * HW;
                const float4 f = g_B4[q];
                S0 -= f.x; S1 -= f.y; S2 -= f.z; S3 -= f.w;
                S4 -= g_B1[q];
            }
        }

#pragma unroll
        for (int o = 16; o > 0; o >>= 1)
            local += __shfl_down_sync(0xffffffffu, local, o);

        __shared__ float wsum[8];
        if ((t & 31) == 0) wsum[t >> 5] = local;
        __syncthreads();
        if (t == 0) {
            float s = 0.f;
#pragma unroll
            for (int i = 0; i < 8; i++) s += wsum[i];
            g_part[partC * K3_BLK + bidC] = (double)s;
        }
    }
}

// ---------------------------------------------------------------------------
// Final: parallel deterministic reduction of all phase partials.
// ---------------------------------------------------------------------------
__global__ __launch_bounds__(256) void k_final(float* __restrict__ out) {
    __shared__ double sd[256];
    const int t = threadIdx.x;
    double s = 0.0;
    for (int i = t; i < NPART_TOT; i += 256) s += g_part[i];
    sd[t] = s;
    __syncthreads();
#pragma unroll
    for (int o = 128; o > 0; o >>= 1) {
        if (t < o) sd[t] += sd[t + o];
        __syncthreads();
    }
    if (t == 0) out[0] = (float)(-sd[0] / (double)VOLI);
}

extern "C" void kernel_launch(void* const* d_in, const int* in_sizes, int n_in,
                              void* d_out, int out_size) {
    const float* I = (const float*)d_in[0];   // y_true
    const float* J = (const float*)d_in[1];   // y_pred

    // L1: kA planes d in [0,60)                       360 blocks
    fusedAB<<<360, 256>>>(I, J, 0, 60, 360, 0, 0, 0);
    // L2: kA d in [60,112) (312) || k3 outputs [0,56)  (336)
    fusedAB<<<312 + K3_BLK, 256>>>(I, J, 60, 52, 312, 0, 56, 0);
    // L3: kA d in [112,160) (288) || k3 outputs [56,108) (336)
    fusedAB<<<288 + K3_BLK, 256>>>(I, J, 112, 48, 288, 56, 108, 1);
    // L4: k3 outputs [108,160)                         336 blocks
    fusedAB<<<K3_BLK, 256>>>(I, J, 0, 1, 0, 108, 160, 2);

    k_final<<<1, 256>>>((float*)d_out);
}

// round 11
// speedup vs baseline: 1.0786x; 1.0786x over previous
#include <cuda_runtime.h>

// Geometry: (N=2, C=1, D=160, H=192, W=224), win=9, pad=4, zero-padded box sums.
#define NB   2
#define DD   160
#define HH   192
#define WW   224
#define HW   (HH * WW)            // 43008
#define DHW  (DD * HW)            // 6881280
#define VOLI (NB * DHW)           // 13762560
#define PAD  4
#define EPSV 1e-5f
#define SZ   ((size_t)VOLI)

#define CH     64                 // h-chunk per block in kA
#define NSTEPS (CH + 2 * PAD)     // 72
#define ROWL   (WW + 2 * PAD)     // 232

#define CHD  80                   // d-chunk per thread in k3
#define NCD  2
#define T3   (NB * NCD * HH * WW) // 172032
#define K3_BLOCKS (T3 / 256)      // 672

// Scratch: W+H box-summed fields. float4 = (sumI,sumJ,sumI2,sumJ2), float = sumIJ.
__device__ float4 g_B4[SZ];
__device__ float  g_B1[SZ];
__device__ double g_part[K3_BLOCKS];

// ---------------------------------------------------------------------------
// kA: fused W-pass + H-pass, software-pipelined, H-ring in SHARED MEMORY.
// (R7 version verbatim — fastest measured configuration.)
// ---------------------------------------------------------------------------
__global__ __launch_bounds__(256) void kA(const float* __restrict__ I,
                                          const float* __restrict__ J) {
    __shared__ float4 ringQ[9][ROWL];   // 33,408 B : (v0,v1,v2,v3) history
    __shared__ float  ringS[9][ROWL];   //  8,352 B : v4 history
    __shared__ float  sI[2][ROWL];      //  1,856 B
    __shared__ float  sJ[2][ROWL];      //  1,856 B

    const int t = threadIdx.x;
    const int plane = blockIdx.x;              // n*DD + d
    const int h0 = blockIdx.y * CH;
    const float* Ip = I + (size_t)plane * HW;
    const float* Jp = J + (size_t)plane * HW;
    const size_t obase = (size_t)plane * HW;

    const int wld = t - PAD;                   // column this thread loads (halo)
    const bool lane_ok = (t < ROWL);
    const bool ld_ok = lane_ok && ((unsigned)wld < (unsigned)WW);

    // Zero-init ring (column-private; visibility guaranteed by step-0 barrier).
    if (t < ROWL) {
#pragma unroll
        for (int s = 0; s < 9; s++) {
            ringQ[s][t] = make_float4(0.f, 0.f, 0.f, 0.f);
            ringS[s][t] = 0.f;
        }
    }

    float S0 = 0.f, S1 = 0.f, S2 = 0.f, S3 = 0.f, S4 = 0.f;

    // Prefetch step 0 (row h0 - PAD)
    float vi = 0.f, vj = 0.f;
    {
        const int hh = h0 - PAD;
        if (ld_ok && (unsigned)hh < (unsigned)HH) {
            const size_t p = (size_t)hh * WW + wld;
            vi = Ip[p]; vj = Jp[p];
        }
    }

    int rs = 0;                                // ring slot = step % 9
#pragma unroll 2
    for (int step = 0; step < NSTEPS; step++) {
        const int buf = step & 1;

        // publish prefetched row
        if (lane_ok) {
            sI[buf][t] = vi;
            sJ[buf][t] = vj;
        }

        // prefetch next row (independent of smem/compute)
        {
            const int hh = h0 - PAD + step + 1;
            vi = 0.f; vj = 0.f;
            if (ld_ok && (unsigned)hh < (unsigned)HH) {
                const size_t p = (size_t)hh * WW + wld;
                vi = Ip[p]; vj = Jp[p];
            }
        }

        __syncthreads();

        if (t < WW) {
            float v0 = 0.f, v1 = 0.f, v2 = 0.f, v3 = 0.f, v4 = 0.f;
#pragma unroll
            for (int q = 0; q < 9; q++) {
                const float a = sI[buf][t + q];
                const float b = sJ[buf][t + q];
                v0 += a; v1 += b;
                v2 += a * a; v3 += b * b; v4 += a * b;
            }
            // H sliding window via smem ring (own column only)
            const float4 o4 = ringQ[rs][t];
            const float  o1 = ringS[rs][t];
            S0 += v0 - o4.x;
            S1 += v1 - o4.y;
            S2 += v2 - o4.z;
            S3 += v3 - o4.w;
            S4 += v4 - o1;
            ringQ[rs][t] = make_float4(v0, v1, v2, v3);
            ringS[rs][t] = v4;

            if (step >= 2 * PAD) {
                const int ho = h0 + step - 2 * PAD;
                const size_t idx = obase + (size_t)ho * WW + t;
                g_B4[idx] = make_float4(S0, S1, S2, S3);
                g_B1[idx] = S4;
            }
        }
        rs = (rs == 8) ? 0 : rs + 1;
        // no second sync: next step's barrier separates row-buffer reuse
    }
}

// ---------------------------------------------------------------------------
// k3: D-axis sliding box sum fused with NCC pointwise loss + block reduction.
// NEW: 9-plane history in a REGISTER ring with static slots (outer loop in
// groups of 9, inner fully unrolled). Every g_B element is read from global
// exactly once; the sub-side is a register read, removing ~275 MB of L2
// traffic and all ring LDS/STS.
// ---------------------------------------------------------------------------
__global__ __launch_bounds__(256) void k3_dpass() {
    const int tid = threadIdx.x;
    const int t = blockIdx.x * 256 + tid;      // grid is exact: t < T3

    int w = t % WW;
    int r = t / WW;
    int h = r % HH; r /= HH;
    const int chunk = r & (NCD - 1);           // uniform per block (168 blocks per (n,chunk))
    const int n = r >> 1;
    const int d0 = chunk * CHD;
    const int dend = d0 + CHD;
    const size_t base = (size_t)n * DHW + (size_t)h * WW + w;

    float4 Q[9];
    float  G[9];
    float S0 = 0.f, S1 = 0.f, S2 = 0.f, S3 = 0.f, S4 = 0.f;

    // Initial window [d0-4, d0+4]; plane (d0-4+k) lives in slot k.
#pragma unroll
    for (int k = 0; k < 9; k++) {
        const int dd = d0 - PAD + k;
        float4 f = make_float4(0.f, 0.f, 0.f, 0.f);
        float  g = 0.f;
        if ((unsigned)dd < (unsigned)DD) {
            const size_t p = base + (size_t)dd * HW;
            f = g_B4[p];
            g = g_B1[p];
        }
        Q[k] = f; G[k] = g;
        S0 += f.x; S1 += f.y; S2 += f.z; S3 += f.w; S4 += g;
    }

    const float ws = 729.f, inv_ws = 1.f / 729.f;
    float local = 0.f;

    for (int grp = 0; grp < 9; grp++) {
#pragma unroll
        for (int k = 0; k < 9; k++) {
            const int d = d0 + grp * 9 + k;    // ring slot = (d - d0) % 9 = k
            if (d < dend) {                    // uniform guard
                const float ui = S0 * inv_ws;
                const float uj = S1 * inv_ws;
                const float cross = S4 - uj * S0 - ui * S1 + ui * uj * ws;
                const float iv = fmaxf(S2 - 2.f * ui * S0 + ui * ui * ws, EPSV);
                const float jv = fmaxf(S3 - 2.f * uj * S1 + uj * uj * ws, EPSV);
                local += (cross * cross) / (iv * jv);

                if (d + 1 < dend) {            // skip dead last add (uniform)
                    const int da = d + PAD + 1;
                    float4 f = make_float4(0.f, 0.f, 0.f, 0.f);
                    float  g = 0.f;
                    if (da < DD) {
                        const size_t q = base + (size_t)da * HW;
                        f = g_B4[q];
                        g = g_B1[q];
                    }
                    S0 += f.x - Q[k].x;
                    S1 += f.y - Q[k].y;
                    S2 += f.z - Q[k].z;
                    S3 += f.w - Q[k].w;
                    S4 += g   - G[k];
                    Q[k] = f; G[k] = g;
                }
            }
        }
    }

#pragma unroll
    for (int o = 16; o > 0; o >>= 1)
        local += __shfl_down_sync(0xffffffffu, local, o);

    __shared__ float wsum[8];
    if ((tid & 31) == 0) wsum[tid >> 5] = local;
    __syncthreads();
    if (tid == 0) {
        float s = 0.f;
#pragma unroll
        for (int i = 0; i < 8; i++) s += wsum[i];
        g_part[blockIdx.x] = (double)s;
    }
}

// ---------------------------------------------------------------------------
// Final: parallel deterministic reduction of 672 partials.
// ---------------------------------------------------------------------------
__global__ __launch_bounds__(256) void k_final(float* __restrict__ out) {
    __shared__ double sd[256];
    const int t = threadIdx.x;
    double s = 0.0;
    for (int i = t; i < K3_BLOCKS; i += 256) s += g_part[i];
    sd[t] = s;
    __syncthreads();
#pragma unroll
    for (int o = 128; o > 0; o >>= 1) {
        if (t < o) sd[t] += sd[t + o];
        __syncthreads();
    }
    if (t == 0) out[0] = (float)(-sd[0] / (double)VOLI);
}

extern "C" void kernel_launch(void* const* d_in, const int* in_sizes, int n_in,
                              void* d_out, int out_size) {
    const float* I = (const float*)d_in[0];   // y_true
    const float* J = (const float*)d_in[1];   // y_pred

    dim3 gridA(NB * DD, HH / CH);             // (320, 3)
    kA<<<gridA, 256>>>(I, J);
    k3_dpass<<<K3_BLOCKS, 256>>>();
    k_final<<<1, 256>>>((float*)d_out);
}

// round 12
// speedup vs baseline: 1.3910x; 1.2897x over previous
#include <cuda_runtime.h>
#include <cuda_fp16.h>

// Geometry: (N=2, C=1, D=160, H=192, W=224), win=9, pad=4, zero-padded box sums.
#define NB   2
#define DD   160
#define HH   192
#define WW   224
#define HW   (HH * WW)            // 43008
#define DHW  (DD * HW)            // 6881280
#define VOLI (NB * DHW)           // 13762560
#define PAD  4
#define EPSV 1e-5f
#define SZ   ((size_t)VOLI)

#define CH     64                 // h-chunk per block in kA
#define NSTEPS (CH + 2 * PAD)     // 72
#define ROWL   (WW + 2 * PAD)     // 232

#define CHD  80                   // d-chunk per thread in k3
#define NCD  2
#define T3   (NB * NCD * HH * WW) // 172032
#define K3_BLOCKS (T3 / 256)      // 672

// Scratch: W+H box-summed fields in FP16 (values <= 81, fits easily).
// 3 streams: (S0,S1) half2, (S2,S3) half2, S4 half  -> 10 B/voxel (was 20).
__device__ __half2 g_H01[SZ];
__device__ __half2 g_H23[SZ];
__device__ __half  g_H4[SZ];
__device__ double  g_part[K3_BLOCKS];

// ---------------------------------------------------------------------------
// kA: fused W-pass + H-pass, software-pipelined, H-ring in SHARED MEMORY.
// (R7 algorithm; epilogue stores fp16.)
// ---------------------------------------------------------------------------
__global__ __launch_bounds__(256) void kA(const float* __restrict__ I,
                                          const float* __restrict__ J) {
    __shared__ float4 ringQ[9][ROWL];   // 33,408 B : (v0,v1,v2,v3) history
    __shared__ float  ringS[9][ROWL];   //  8,352 B : v4 history
    __shared__ float  sI[2][ROWL];      //  1,856 B
    __shared__ float  sJ[2][ROWL];      //  1,856 B

    const int t = threadIdx.x;
    const int plane = blockIdx.x;              // n*DD + d
    const int h0 = blockIdx.y * CH;
    const float* Ip = I + (size_t)plane * HW;
    const float* Jp = J + (size_t)plane * HW;
    const size_t obase = (size_t)plane * HW;

    const int wld = t - PAD;                   // column this thread loads (halo)
    const bool lane_ok = (t < ROWL);
    const bool ld_ok = lane_ok && ((unsigned)wld < (unsigned)WW);

    // Zero-init ring (column-private; visibility guaranteed by step-0 barrier).
    if (t < ROWL) {
#pragma unroll
        for (int s = 0; s < 9; s++) {
            ringQ[s][t] = make_float4(0.f, 0.f, 0.f, 0.f);
            ringS[s][t] = 0.f;
        }
    }

    float S0 = 0.f, S1 = 0.f, S2 = 0.f, S3 = 0.f, S4 = 0.f;

    // Prefetch step 0 (row h0 - PAD)
    float vi = 0.f, vj = 0.f;
    {
        const int hh = h0 - PAD;
        if (ld_ok && (unsigned)hh < (unsigned)HH) {
            const size_t p = (size_t)hh * WW + wld;
            vi = Ip[p]; vj = Jp[p];
        }
    }

    int rs = 0;                                // ring slot = step % 9
#pragma unroll 2
    for (int step = 0; step < NSTEPS; step++) {
        const int buf = step & 1;

        // publish prefetched row
        if (lane_ok) {
            sI[buf][t] = vi;
            sJ[buf][t] = vj;
        }

        // prefetch next row (independent of smem/compute)
        {
            const int hh = h0 - PAD + step + 1;
            vi = 0.f; vj = 0.f;
            if (ld_ok && (unsigned)hh < (unsigned)HH) {
                const size_t p = (size_t)hh * WW + wld;
                vi = Ip[p]; vj = Jp[p];
            }
        }

        __syncthreads();

        if (t < WW) {
            float v0 = 0.f, v1 = 0.f, v2 = 0.f, v3 = 0.f, v4 = 0.f;
#pragma unroll
            for (int q = 0; q < 9; q++) {
                const float a = sI[buf][t + q];
                const float b = sJ[buf][t + q];
                v0 += a; v1 += b;
                v2 += a * a; v3 += b * b; v4 += a * b;
            }
            // H sliding window via smem ring (own column only)
            const float4 o4 = ringQ[rs][t];
            const float  o1 = ringS[rs][t];
            S0 += v0 - o4.x;
            S1 += v1 - o4.y;
            S2 += v2 - o4.z;
            S3 += v3 - o4.w;
            S4 += v4 - o1;
            ringQ[rs][t] = make_float4(v0, v1, v2, v3);
            ringS[rs][t] = v4;

            if (step >= 2 * PAD) {
                const int ho = h0 + step - 2 * PAD;
                const size_t idx = obase + (size_t)ho * WW + t;
                g_H01[idx] = __floats2half2_rn(S0, S1);
                g_H23[idx] = __floats2half2_rn(S2, S3);
                g_H4[idx]  = __float2half_rn(S4);
            }
        }
        rs = (rs == 8) ? 0 : rs + 1;
        // no second sync: next step's barrier separates row-buffer reuse
    }
}

// ---------------------------------------------------------------------------
// k3: D-axis sliding box sum fused with NCC pointwise loss + block reduction.
// (R7 algorithm — plain add/sub re-read; loads fp16, math in fp32.)
// ---------------------------------------------------------------------------
__global__ __launch_bounds__(256) void k3_dpass() {
    const int tid = threadIdx.x;
    const int t = blockIdx.x * 256 + tid;
    float local = 0.f;

    if (t < T3) {
        int w = t % WW;
        int r = t / WW;
        int h = r % HH; r /= HH;
        int chunk = r & (NCD - 1);
        int n = r >> 1;
        int d0 = chunk * CHD;
        size_t base = (size_t)n * DHW + (size_t)h * WW + w;

        float S0 = 0.f, S1 = 0.f, S2 = 0.f, S3 = 0.f, S4 = 0.f;
#pragma unroll
        for (int k = -PAD; k <= PAD; k++) {
            int dd = d0 + k;
            if ((unsigned)dd < (unsigned)DD) {
                size_t p = base + (size_t)dd * HW;
                const float2 a = __half22float2(g_H01[p]);
                const float2 b = __half22float2(g_H23[p]);
                S0 += a.x; S1 += a.y; S2 += b.x; S3 += b.y;
                S4 += __half2float(g_H4[p]);
            }
        }

        const float ws = 729.f, inv_ws = 1.f / 729.f;

#pragma unroll 4
        for (int d = d0; d < d0 + CHD; d++) {
            float ui = S0 * inv_ws;
            float uj = S1 * inv_ws;
            float cross = S4 - uj * S0 - ui * S1 + ui * uj * ws;
            float iv = fmaxf(S2 - 2.f * ui * S0 + ui * ui * ws, EPSV);
            float jv = fmaxf(S3 - 2.f * uj * S1 + uj * uj * ws, EPSV);
            local += (cross * cross) / (iv * jv);

            int da = d + PAD + 1;
            int ds = d - PAD;
            if (da < DD) {
                size_t q = base + (size_t)da * HW;
                const float2 a = __half22float2(g_H01[q]);
                const float2 b = __half22float2(g_H23[q]);
                S0 += a.x; S1 += a.y; S2 += b.x; S3 += b.y;
                S4 += __half2float(g_H4[q]);
            }
            if (ds >= 0) {
                size_t q = base + (size_t)ds * HW;
                const float2 a = __half22float2(g_H01[q]);
                const float2 b = __half22float2(g_H23[q]);
                S0 -= a.x; S1 -= a.y; S2 -= b.x; S3 -= b.y;
                S4 -= __half2float(g_H4[q]);
            }
        }
    }

#pragma unroll
    for (int o = 16; o > 0; o >>= 1)
        local += __shfl_down_sync(0xffffffffu, local, o);

    __shared__ float wsum[8];
    if ((tid & 31) == 0) wsum[tid >> 5] = local;
    __syncthreads();
    if (tid == 0) {
        float s = 0.f;
#pragma unroll
        for (int i = 0; i < 8; i++) s += wsum[i];
        g_part[blockIdx.x] = (double)s;
    }
}

// ---------------------------------------------------------------------------
// Final: parallel deterministic reduction of 672 partials.
// ---------------------------------------------------------------------------
__global__ __launch_bounds__(256) void k_final(float* __restrict__ out) {
    __shared__ double sd[256];
    const int t = threadIdx.x;
    double s = 0.0;
    for (int i = t; i < K3_BLOCKS; i += 256) s += g_part[i];
    sd[t] = s;
    __syncthreads();
#pragma unroll
    for (int o = 128; o > 0; o >>= 1) {
        if (t < o) sd[t] += sd[t + o];
        __syncthreads();
    }
    if (t == 0) out[0] = (float)(-sd[0] / (double)VOLI);
}

extern "C" void kernel_launch(void* const* d_in, const int* in_sizes, int n_in,
                              void* d_out, int out_size) {
    const float* I = (const float*)d_in[0];   // y_true
    const float* J = (const float*)d_in[1];   // y_pred

    dim3 gridA(NB * DD, HH / CH);             // (320, 3)
    kA<<<gridA, 256>>>(I, J);
    k3_dpass<<<K3_BLOCKS, 256>>>();
    k_final<<<1, 256>>>((float*)d_out);
}